// round 1
// baseline (speedup 1.0000x reference)
#include <cuda_runtime.h>

#define NSTATE 1024
#define NHEAD  16
#define HDIM   64
#define TMAX   6144

// Scratch (device globals: allocation-free rule)
__device__ float g_q[TMAX * NSTATE];
__device__ float g_k[TMAX * NSTATE];
__device__ float g_v[TMAX * NSTATE];
__device__ float g_ctx[TMAX * NSTATE];

// ---------------------------------------------------------------------------
// SGEMM NT: C[M,N] = A[M,K] @ W[N,K]^T (+ bias). BM=BN=128, BK=16, 256 thr,
// 8x8 per-thread tile. Assumes M%128==0, N%128==0, K%16==0 (true here).
// ---------------------------------------------------------------------------
__device__ __forceinline__ void sgemm_body(const float* __restrict__ A,
                                           const float* __restrict__ W,
                                           const float* __restrict__ bias,
                                           float* __restrict__ C,
                                           int M, int N, int K)
{
    __shared__ float As[16][128];
    __shared__ float Bs[16][128];

    const int tid = threadIdx.x;
    const int tx = tid & 15;        // N direction
    const int ty = tid >> 4;        // M direction
    const int bm = blockIdx.y * 128;
    const int bn = blockIdx.x * 128;

    const int lrow = tid >> 1;      // 0..127
    const int lk   = (tid & 1) * 8; // 0 or 8

    const float* Ag = A + (size_t)(bm + lrow) * K + lk;
    const float* Wg = W + (size_t)(bn + lrow) * K + lk;

    float acc[8][8];
#pragma unroll
    for (int i = 0; i < 8; i++)
#pragma unroll
        for (int j = 0; j < 8; j++) acc[i][j] = 0.f;

    for (int k0 = 0; k0 < K; k0 += 16) {
        float4 a0 = *(const float4*)(Ag + k0);
        float4 a1 = *(const float4*)(Ag + k0 + 4);
        float4 w0 = *(const float4*)(Wg + k0);
        float4 w1 = *(const float4*)(Wg + k0 + 4);

        __syncthreads();  // previous iteration's reads done
        As[lk + 0][lrow] = a0.x; As[lk + 1][lrow] = a0.y;
        As[lk + 2][lrow] = a0.z; As[lk + 3][lrow] = a0.w;
        As[lk + 4][lrow] = a1.x; As[lk + 5][lrow] = a1.y;
        As[lk + 6][lrow] = a1.z; As[lk + 7][lrow] = a1.w;
        Bs[lk + 0][lrow] = w0.x; Bs[lk + 1][lrow] = w0.y;
        Bs[lk + 2][lrow] = w0.z; Bs[lk + 3][lrow] = w0.w;
        Bs[lk + 4][lrow] = w1.x; Bs[lk + 5][lrow] = w1.y;
        Bs[lk + 6][lrow] = w1.z; Bs[lk + 7][lrow] = w1.w;
        __syncthreads();

#pragma unroll
        for (int kk = 0; kk < 16; kk++) {
            float a[8], b[8];
            *(float4*)&a[0] = *(const float4*)&As[kk][ty * 8];
            *(float4*)&a[4] = *(const float4*)&As[kk][ty * 8 + 4];
            *(float4*)&b[0] = *(const float4*)&Bs[kk][tx * 8];
            *(float4*)&b[4] = *(const float4*)&Bs[kk][tx * 8 + 4];
#pragma unroll
            for (int i = 0; i < 8; i++)
#pragma unroll
                for (int j = 0; j < 8; j++)
                    acc[i][j] = fmaf(a[i], b[j], acc[i][j]);
        }
    }

    float bb[8];
#pragma unroll
    for (int j = 0; j < 8; j++) bb[j] = bias ? bias[bn + tx * 8 + j] : 0.f;

#pragma unroll
    for (int i = 0; i < 8; i++) {
        const int row = bm + ty * 8 + i;
        float* Cp = C + (size_t)row * N + bn + tx * 8;
        float4 c0, c1;
        c0.x = acc[i][0] + bb[0]; c0.y = acc[i][1] + bb[1];
        c0.z = acc[i][2] + bb[2]; c0.w = acc[i][3] + bb[3];
        c1.x = acc[i][4] + bb[4]; c1.y = acc[i][5] + bb[5];
        c1.z = acc[i][6] + bb[6]; c1.w = acc[i][7] + bb[7];
        *(float4*)(Cp)     = c0;
        *(float4*)(Cp + 4) = c1;
    }
}

__global__ __launch_bounds__(256)
void qkv_kernel(const float* __restrict__ x,
                const float* __restrict__ Wq, const float* __restrict__ bq,
                const float* __restrict__ Wk,
                const float* __restrict__ Wv, const float* __restrict__ bv,
                int M)
{
    if (blockIdx.z == 0)       sgemm_body(x, Wq, bq,      g_q, M, NSTATE, NSTATE);
    else if (blockIdx.z == 1)  sgemm_body(x, Wk, nullptr, g_k, M, NSTATE, NSTATE);
    else                       sgemm_body(x, Wv, bv,      g_v, M, NSTATE, NSTATE);
}

__global__ __launch_bounds__(256)
void oproj_kernel(const float* __restrict__ Wo, const float* __restrict__ bo,
                  float* __restrict__ out, int M)
{
    sgemm_body(g_ctx, Wo, bo, out, M, NSTATE, NSTATE);
}

// ---------------------------------------------------------------------------
// Flash attention: one CTA per (64-query tile, head). Online softmax over
// 64-key tiles. Non-causal, ragged sequences via cu_seqlens.
// 256 threads: tx=tid&15 (key/dim cols, 4 each), ty=tid>>4 (query rows, 4 each)
// ---------------------------------------------------------------------------
__global__ __launch_bounds__(256)
void attn_kernel(const int* __restrict__ cu, int nseq)
{
    extern __shared__ float sm[];
    float (*Qs)[65] = (float(*)[65])(sm);
    float (*Ks)[65] = (float(*)[65])(sm + 64 * 65);
    float (*Vs)[65] = (float(*)[65])(sm + 2 * 64 * 65);
    float (*Ps)[65] = (float(*)[65])(sm + 3 * 64 * 65);

    const int h = blockIdx.y;

    // map blockIdx.x -> (sequence, query tile)
    int s0 = 0, L = 0, q0 = 0, found = 0;
    {
        int acct = 0;
        const int gt = blockIdx.x;
        for (int b = 0; b < nseq; b++) {
            const int s = cu[b], e = cu[b + 1];
            const int Lb = e - s;
            const int nt = (Lb + 63) >> 6;
            if (gt < acct + nt) { s0 = s; L = Lb; q0 = s + (gt - acct) * 64; found = 1; break; }
            acct += nt;
        }
    }
    if (!found) return;

    const int tid = threadIdx.x;
    const int tx = tid & 15, ty = tid >> 4;
    const int qrows = min(64, s0 + L - q0);

    // load Q tile, fold in softmax scale 1/sqrt(64)
#pragma unroll
    for (int it = 0; it < 16; it++) {
        const int idx = tid + it * 256;
        const int r = idx >> 6, c = idx & 63;
        Qs[r][c] = (r < qrows) ? g_q[(size_t)(q0 + r) * NSTATE + h * HDIM + c] * 0.125f : 0.f;
    }

    float m_i[4], l_i[4], o[4][4];
#pragma unroll
    for (int i = 0; i < 4; i++) {
        m_i[i] = -1e30f; l_i[i] = 0.f;
#pragma unroll
        for (int j = 0; j < 4; j++) o[i][j] = 0.f;
    }

    const int nkt = (L + 63) >> 6;
    for (int kt = 0; kt < nkt; kt++) {
        const int kbase = kt * 64;
        const int kc = min(64, L - kbase);

        __syncthreads();  // also covers Q-load on first iter; protects Ps/Vs reuse
#pragma unroll
        for (int it = 0; it < 16; it++) {
            const int idx = tid + it * 256;
            const int r = idx >> 6, c = idx & 63;
            const bool ok = (r < kc);
            const size_t g = (size_t)(s0 + kbase + r) * NSTATE + h * HDIM + c;
            Ks[r][c] = ok ? g_k[g] : 0.f;
            Vs[r][c] = ok ? g_v[g] : 0.f;
        }
        __syncthreads();

        // S = Q K^T (scale already in Q)
        float s[4][4];
#pragma unroll
        for (int i = 0; i < 4; i++)
#pragma unroll
            for (int j = 0; j < 4; j++) s[i][j] = 0.f;

#pragma unroll 16
        for (int d = 0; d < 64; d++) {
            float a[4], b[4];
#pragma unroll
            for (int i = 0; i < 4; i++) a[i] = Qs[ty * 4 + i][d];
#pragma unroll
            for (int j = 0; j < 4; j++) b[j] = Ks[tx * 4 + j][d];
#pragma unroll
            for (int i = 0; i < 4; i++)
#pragma unroll
                for (int j = 0; j < 4; j++)
                    s[i][j] = fmaf(a[i], b[j], s[i][j]);
        }

        if (kc < 64) {
#pragma unroll
            for (int j = 0; j < 4; j++)
                if (tx * 4 + j >= kc) {
#pragma unroll
                    for (int i = 0; i < 4; i++) s[i][j] = -1e30f;
                }
        }

        // online softmax (row stats all-reduced over the 16 tx lanes)
#pragma unroll
        for (int i = 0; i < 4; i++) {
            float mt = fmaxf(fmaxf(s[i][0], s[i][1]), fmaxf(s[i][2], s[i][3]));
#pragma unroll
            for (int msk = 1; msk < 16; msk <<= 1)
                mt = fmaxf(mt, __shfl_xor_sync(0xffffffffu, mt, msk));
            const float mn = fmaxf(m_i[i], mt);
            const float alpha = __expf(m_i[i] - mn);
            float r = 0.f;
#pragma unroll
            for (int j = 0; j < 4; j++) { s[i][j] = __expf(s[i][j] - mn); r += s[i][j]; }
#pragma unroll
            for (int msk = 1; msk < 16; msk <<= 1)
                r += __shfl_xor_sync(0xffffffffu, r, msk);
            l_i[i] = l_i[i] * alpha + r;
            m_i[i] = mn;
#pragma unroll
            for (int j = 0; j < 4; j++) o[i][j] *= alpha;
        }

        // write P, then O += P @ V
#pragma unroll
        for (int i = 0; i < 4; i++)
#pragma unroll
            for (int j = 0; j < 4; j++) Ps[ty * 4 + i][tx * 4 + j] = s[i][j];
        __syncthreads();

#pragma unroll 16
        for (int j = 0; j < 64; j++) {
            float p[4], vv[4];
#pragma unroll
            for (int i = 0; i < 4; i++) p[i] = Ps[ty * 4 + i][j];
#pragma unroll
            for (int b = 0; b < 4; b++) vv[b] = Vs[j][tx * 4 + b];
#pragma unroll
            for (int i = 0; i < 4; i++)
#pragma unroll
                for (int b = 0; b < 4; b++)
                    o[i][b] = fmaf(p[i], vv[b], o[i][b]);
        }
    }

    // normalize and write ctx
#pragma unroll
    for (int i = 0; i < 4; i++) {
        const int r = ty * 4 + i;
        if (r < qrows) {
            const float inv = 1.f / l_i[i];
            float* cp = &g_ctx[(size_t)(q0 + r) * NSTATE + h * HDIM + tx * 4];
#pragma unroll
            for (int j = 0; j < 4; j++) cp[j] = o[i][j] * inv;
        }
    }
}

// ---------------------------------------------------------------------------
// Launch. Inputs: 0=x, 1=cu_seqlens, 2=Wq, 3=bq, 4=Wk, 5=Wv, 6=bv, 7=Wo, 8=bo
// ---------------------------------------------------------------------------
extern "C" void kernel_launch(void* const* d_in, const int* in_sizes, int n_in,
                              void* d_out, int out_size)
{
    const float* x  = (const float*)d_in[0];
    const int*   cu = (const int*)d_in[1];
    const float* Wq = (const float*)d_in[2];
    const float* bq = (const float*)d_in[3];
    const float* Wk = (const float*)d_in[4];
    const float* Wv = (const float*)d_in[5];
    const float* bv = (const float*)d_in[6];
    const float* Wo = (const float*)d_in[7];
    const float* bo = (const float*)d_in[8];

    const int T = in_sizes[0] / NSTATE;       // 6144
    const int nseq = in_sizes[1] - 1;         // 8

    const int attn_smem = 4 * 64 * 65 * (int)sizeof(float);  // 66560 B
    cudaFuncSetAttribute(attn_kernel,
                         cudaFuncAttributeMaxDynamicSharedMemorySize, attn_smem);

    dim3 gqkv(NSTATE / 128, T / 128, 3);
    qkv_kernel<<<gqkv, 256>>>(x, Wq, bq, Wk, Wv, bv, T);

    const int maxTiles = T / 64 + nseq;       // upper bound on sum(ceil(L/64))
    dim3 gattn(maxTiles, NHEAD);
    attn_kernel<<<gattn, 256, attn_smem>>>(cu, nseq);

    dim3 go(NSTATE / 128, T / 128);
    oproj_kernel<<<go, 256>>>(Wo, bo, (float*)d_out, T);
}